// round 1
// baseline (speedup 1.0000x reference)
#include <cuda_runtime.h>
#include <math.h>

// ---------------- constants ----------------
#define BQ     16
#define GRID   64          // Hg = Wg
#define DIMC   512
#define NHEAD  16
#define HD     32
#define WSZ    8
#define SHIFT_ 4
#define NTOK   64          // tokens per window
#define ROWS   65536       // B * L
#define HID    2048
#define QKVC   1536

// ---------------- scratch ----------------
__device__ float g_yw [ (size_t)ROWS * DIMC ];   // LN1 output, window order
__device__ float g_mw [ ROWS ];                  // clipped prior, window order
__device__ float g_qkv[ (size_t)ROWS * QKVC ];   // qkv, window order
__device__ float g_ao [ (size_t)ROWS * DIMC ];   // attention output, window order
__device__ float g_x1 [ (size_t)ROWS * DIMC ];   // shortcut + proj, (b,l) order
__device__ float g_ln2[ (size_t)ROWS * DIMC ];   // LN2 output, (b,l) order
__device__ float g_h  [ (size_t)ROWS * HID  ];   // fc1+gelu output

// ---------------- LN1 + shift + window partition ----------------
__global__ __launch_bounds__(256) void ln1_win_kernel(
    const float* __restrict__ x, const float* __restrict__ Mmap,
    const float* __restrict__ gamma, const float* __restrict__ beta)
{
    int warp = threadIdx.x >> 5, lane = threadIdx.x & 31;
    int row  = (blockIdx.x << 3) + warp;          // window-order row
    int bq   = row >> 12, local = row & 4095;
    int wloc = local >> 6, t = local & 63;
    int hh = (((wloc >> 3) << 3) + (t >> 3) + SHIFT_) & 63;  // original h
    int ww = (((wloc &  7) << 3) + (t &  7) + SHIFT_) & 63;  // original w
    size_t src = ((size_t)bq * 4096 + (size_t)hh * 64 + ww) * DIMC;

    const float4* xp = (const float4*)(x + src);
    float v[16];
    float s = 0.f, ss = 0.f;
#pragma unroll
    for (int i = 0; i < 4; i++) {
        float4 f = xp[i * 32 + lane];
        v[i*4+0]=f.x; v[i*4+1]=f.y; v[i*4+2]=f.z; v[i*4+3]=f.w;
        s  += f.x + f.y + f.z + f.w;
        ss += f.x*f.x + f.y*f.y + f.z*f.z + f.w*f.w;
    }
#pragma unroll
    for (int o = 16; o; o >>= 1) {
        s  += __shfl_xor_sync(0xffffffffu, s,  o);
        ss += __shfl_xor_sync(0xffffffffu, ss, o);
    }
    float mean = s * (1.f/512.f);
    float var  = ss * (1.f/512.f) - mean * mean;
    float rstd = rsqrtf(var + 1e-5f);

    float4* yp = (float4*)(g_yw + (size_t)row * DIMC);
    const float4* gp = (const float4*)gamma;
    const float4* bp = (const float4*)beta;
#pragma unroll
    for (int i = 0; i < 4; i++) {
        float4 g4 = gp[i*32+lane], b4 = bp[i*32+lane];
        float4 o4;
        o4.x = (v[i*4+0]-mean)*rstd*g4.x + b4.x;
        o4.y = (v[i*4+1]-mean)*rstd*g4.y + b4.y;
        o4.z = (v[i*4+2]-mean)*rstd*g4.z + b4.z;
        o4.w = (v[i*4+3]-mean)*rstd*g4.w + b4.w;
        yp[i*32+lane] = o4;
    }
    if (lane == 0) {
        float m = Mmap[(size_t)bq * 4096 + (size_t)hh * 64 + ww];
        g_mw[row] = fminf(fmaxf(m, 0.f), 1.f);
    }
}

// ---------------- LN2 ((b,l) order, reads g_x1) ----------------
__global__ __launch_bounds__(256) void ln2_kernel(
    const float* __restrict__ gamma, const float* __restrict__ beta)
{
    int warp = threadIdx.x >> 5, lane = threadIdx.x & 31;
    int row  = (blockIdx.x << 3) + warp;

    const float4* xp = (const float4*)(g_x1 + (size_t)row * DIMC);
    float v[16];
    float s = 0.f, ss = 0.f;
#pragma unroll
    for (int i = 0; i < 4; i++) {
        float4 f = xp[i * 32 + lane];
        v[i*4+0]=f.x; v[i*4+1]=f.y; v[i*4+2]=f.z; v[i*4+3]=f.w;
        s  += f.x + f.y + f.z + f.w;
        ss += f.x*f.x + f.y*f.y + f.z*f.z + f.w*f.w;
    }
#pragma unroll
    for (int o = 16; o; o >>= 1) {
        s  += __shfl_xor_sync(0xffffffffu, s,  o);
        ss += __shfl_xor_sync(0xffffffffu, ss, o);
    }
    float mean = s * (1.f/512.f);
    float var  = ss * (1.f/512.f) - mean * mean;
    float rstd = rsqrtf(var + 1e-5f);

    float4* yp = (float4*)(g_ln2 + (size_t)row * DIMC);
    const float4* gp = (const float4*)gamma;
    const float4* bp = (const float4*)beta;
#pragma unroll
    for (int i = 0; i < 4; i++) {
        float4 g4 = gp[i*32+lane], b4 = bp[i*32+lane];
        float4 o4;
        o4.x = (v[i*4+0]-mean)*rstd*g4.x + b4.x;
        o4.y = (v[i*4+1]-mean)*rstd*g4.y + b4.y;
        o4.z = (v[i*4+2]-mean)*rstd*g4.z + b4.z;
        o4.w = (v[i*4+3]-mean)*rstd*g4.w + b4.w;
        yp[i*32+lane] = o4;
    }
}

// ---------------- generic fp32 GEMM: C = A(MxK) * W(NxK)^T + bias ----------------
// Epilogues: 0 = bias only
//            1 = bias + GELU(exact)
//            2 = bias + window-reverse scatter + residual-from-aux(x), write C in (b,l) order
//            3 = bias + residual-from-aux (same row order), write C
#define EPI_NONE 0
#define EPI_GELU 1
#define EPI_PROJ 2
#define EPI_RES  3

template<int EPI>
__global__ __launch_bounds__(256) void gemm_kernel(
    const float* __restrict__ A, const float* __restrict__ W,
    const float* __restrict__ bias, float* __restrict__ C,
    int M, int N, int K, const float* __restrict__ aux)
{
    __shared__ float As[16][128];
    __shared__ float Bs[16][128];

    int tid = threadIdx.x;
    int m0 = blockIdx.y << 7, n0 = blockIdx.x << 7;
    int ty = tid >> 4, tx = tid & 15;

    float acc[8][8];
#pragma unroll
    for (int i = 0; i < 8; i++)
#pragma unroll
        for (int j = 0; j < 8; j++) acc[i][j] = 0.f;

    for (int k0 = 0; k0 < K; k0 += 16) {
#pragma unroll
        for (int r = 0; r < 2; r++) {
            int f   = (tid << 1) + r;        // 0..511
            int row = f >> 2;
            int kk  = (f & 3) << 2;
            float4 a4 = *(const float4*)(A + (size_t)(m0 + row) * K + (k0 + kk));
            As[kk+0][row] = a4.x; As[kk+1][row] = a4.y;
            As[kk+2][row] = a4.z; As[kk+3][row] = a4.w;
            float4 b4 = *(const float4*)(W + (size_t)(n0 + row) * K + (k0 + kk));
            Bs[kk+0][row] = b4.x; Bs[kk+1][row] = b4.y;
            Bs[kk+2][row] = b4.z; Bs[kk+3][row] = b4.w;
        }
        __syncthreads();
#pragma unroll
        for (int kk = 0; kk < 16; kk++) {
            float a[8], b[8];
            *(float4*)(a)   = *(const float4*)&As[kk][ty*8];
            *(float4*)(a+4) = *(const float4*)&As[kk][ty*8+4];
            *(float4*)(b)   = *(const float4*)&Bs[kk][tx*8];
            *(float4*)(b+4) = *(const float4*)&Bs[kk][tx*8+4];
#pragma unroll
            for (int i = 0; i < 8; i++)
#pragma unroll
                for (int j = 0; j < 8; j++)
                    acc[i][j] += a[i] * b[j];
        }
        __syncthreads();
    }

    // epilogue
    int mbase = m0 + ty * 8;
    int nbase = n0 + tx * 8;
    float bv[8];
#pragma unroll
    for (int j = 0; j < 8; j++) bv[j] = bias[nbase + j];

#pragma unroll
    for (int i = 0; i < 8; i++) {
        int m = mbase + i;
        if (EPI == EPI_PROJ) {
            // window-order row m -> (b, l) in original layout (reverse shift)
            int bq = m >> 12, local = m & 4095;
            int wloc = local >> 6, t = local & 63;
            int hh = (((wloc >> 3) << 3) + (t >> 3) + SHIFT_) & 63;
            int ww = (((wloc &  7) << 3) + (t &  7) + SHIFT_) & 63;
            size_t obase = ((size_t)bq * 4096 + (size_t)hh * 64 + ww) * DIMC;
#pragma unroll
            for (int j = 0; j < 8; j++) {
                float v = acc[i][j] + bv[j];
                size_t o = obase + nbase + j;
                C[o] = aux[o] + v;
            }
        } else {
            size_t obase = (size_t)m * N;
#pragma unroll
            for (int j = 0; j < 8; j++) {
                float v = acc[i][j] + bv[j];
                if (EPI == EPI_GELU)
                    v = 0.5f * v * (1.f + erff(v * 0.70710678118654752f));
                else if (EPI == EPI_RES)
                    v += aux[obase + nbase + j];
                C[obase + nbase + j] = v;
            }
        }
    }
}

// ---------------- attention per (window, head) ----------------
__global__ __launch_bounds__(256) void attn_kernel(const float* __restrict__ rpb_table)
{
    __shared__ float qs[64][33];
    __shared__ float ks[64][33];
    __shared__ float vs[64][33];
    __shared__ float sc[64][65];
    __shared__ float rpb[225];
    __shared__ float mhalf[64];
    __shared__ int   rid[64];

    int w   = blockIdx.x >> 4;     // window id 0..1023
    int h   = blockIdx.x & 15;     // head
    int tid = threadIdx.x;

    size_t base = (size_t)w * 64 * QKVC + (size_t)h * HD;
#pragma unroll
    for (int e = tid; e < 2048; e += 256) {
        int i = e >> 5, d = e & 31;
        size_t o = base + (size_t)i * QKVC + d;
        qs[i][d] = g_qkv[o];
        ks[i][d] = g_qkv[o + 512];
        vs[i][d] = g_qkv[o + 1024];
    }
    for (int e = tid; e < 225; e += 256) rpb[e] = rpb_table[e * NHEAD + h];
    if (tid < 64) {
        mhalf[tid] = 0.5f * g_mw[w * 64 + tid];
        int wloc = w & 63;
        int hr = ((wloc >> 3) << 3) + (tid >> 3);
        int wr = ((wloc & 7)  << 3) + (tid & 7);
        int rh = hr < 56 ? 0 : (hr < 60 ? 1 : 2);
        int rw = wr < 56 ? 0 : (wr < 60 ? 1 : 2);
        rid[tid] = rh * 3 + rw;
    }
    __syncthreads();

    // ---- phase 1: scores ----
    {
        int i  = tid >> 2;
        int j0 = (tid & 3) * 16;
        float qreg[32];
#pragma unroll
        for (int d = 0; d < 32; d++) qreg[d] = qs[i][d];
        int ii = i >> 3, ji = i & 7;
        int ridi = rid[i];
        float mi = mhalf[i];
#pragma unroll 4
        for (int jj = 0; jj < 16; jj++) {
            int j = j0 + jj;
            float a = 0.f;
#pragma unroll
            for (int d = 0; d < 32; d++) a += qreg[d] * ks[j][d];
            int idx = (ii - (j >> 3) + 7) * 15 + (ji - (j & 7) + 7);
            float val = a * 0.17677669529663687f + rpb[idx] + mi + mhalf[j];
            if (ridi != rid[j]) val -= 100.f;
            sc[i][j] = val;
        }
    }
    __syncthreads();

    // ---- phase 2: softmax per row ----
    if (tid < 64) {
        float mx = -1e30f;
#pragma unroll 8
        for (int j = 0; j < 64; j++) mx = fmaxf(mx, sc[tid][j]);
        float ssum = 0.f;
#pragma unroll 8
        for (int j = 0; j < 64; j++) {
            float e = __expf(sc[tid][j] - mx);
            sc[tid][j] = e;
            ssum += e;
        }
        float inv = 1.f / ssum;
#pragma unroll 8
        for (int j = 0; j < 64; j++) sc[tid][j] *= inv;
    }
    __syncthreads();

    // ---- phase 3: P @ V ----
    {
        int oi = tid >> 2;
        int dg = (tid & 3) * 8;
        float acc[8];
#pragma unroll
        for (int d = 0; d < 8; d++) acc[d] = 0.f;
#pragma unroll 8
        for (int j = 0; j < 64; j++) {
            float p = sc[oi][j];
#pragma unroll
            for (int d = 0; d < 8; d++) acc[d] += p * vs[j][dg + d];
        }
        size_t ob = (size_t)(w * 64 + oi) * DIMC + (size_t)h * HD + dg;
#pragma unroll
        for (int d = 0; d < 8; d++) g_ao[ob + d] = acc[d];
    }
}

// ---------------- launcher ----------------
extern "C" void kernel_launch(void* const* d_in, const int* in_sizes, int n_in,
                              void* d_out, int out_size)
{
    (void)in_sizes; (void)n_in; (void)out_size;
    const float* x       = (const float*)d_in[0];
    const float* M_map   = (const float*)d_in[1];
    const float* n1g     = (const float*)d_in[2];
    const float* n1b     = (const float*)d_in[3];
    const float* qkv_w   = (const float*)d_in[4];
    const float* qkv_b   = (const float*)d_in[5];
    const float* proj_w  = (const float*)d_in[6];
    const float* proj_b  = (const float*)d_in[7];
    const float* rpb_t   = (const float*)d_in[8];
    const float* n2g     = (const float*)d_in[9];
    const float* n2b     = (const float*)d_in[10];
    const float* fc1_w   = (const float*)d_in[11];
    const float* fc1_b   = (const float*)d_in[12];
    const float* fc2_w   = (const float*)d_in[13];
    const float* fc2_b   = (const float*)d_in[14];
    float* out = (float*)d_out;

    void *p_yw, *p_qkv, *p_ao, *p_x1, *p_ln2, *p_h;
    cudaGetSymbolAddress(&p_yw,  g_yw);
    cudaGetSymbolAddress(&p_qkv, g_qkv);
    cudaGetSymbolAddress(&p_ao,  g_ao);
    cudaGetSymbolAddress(&p_x1,  g_x1);
    cudaGetSymbolAddress(&p_ln2, g_ln2);
    cudaGetSymbolAddress(&p_h,   g_h);

    // 1) LN1 + shift + window partition (+ prior map)
    ln1_win_kernel<<<ROWS / 8, 256>>>(x, M_map, n1g, n1b);

    // 2) QKV GEMM: (65536 x 512) @ (1536 x 512)^T
    gemm_kernel<EPI_NONE><<<dim3(QKVC / 128, ROWS / 128), 256>>>(
        (const float*)p_yw, qkv_w, qkv_b, (float*)p_qkv, ROWS, QKVC, DIMC, nullptr);

    // 3) windowed attention
    attn_kernel<<<1024 * NHEAD, 256>>>(rpb_t);

    // 4) proj GEMM + window-reverse + residual -> g_x1 (b,l) order
    gemm_kernel<EPI_PROJ><<<dim3(DIMC / 128, ROWS / 128), 256>>>(
        (const float*)p_ao, proj_w, proj_b, (float*)p_x1, ROWS, DIMC, DIMC, x);

    // 5) LN2
    ln2_kernel<<<ROWS / 8, 256>>>(n2g, n2b);

    // 6) fc1 + GELU
    gemm_kernel<EPI_GELU><<<dim3(HID / 128, ROWS / 128), 256>>>(
        (const float*)p_ln2, fc1_w, fc1_b, (float*)p_h, ROWS, HID, DIMC, nullptr);

    // 7) fc2 + residual -> d_out
    gemm_kernel<EPI_RES><<<dim3(DIMC / 128, ROWS / 128), 256>>>(
        (const float*)p_h, fc2_w, fc2_b, out, ROWS, DIMC, HID, (const float*)p_x1);
}

// round 4
// speedup vs baseline: 3.4953x; 3.4953x over previous
#include <cuda_runtime.h>
#include <math.h>
#include <stdint.h>

// ---------------- constants ----------------
#define DIMC   512
#define NHEAD  16
#define HD     32
#define SHIFT_ 4
#define ROWS   65536       // B * L
#define HID    2048
#define QKVC   1536

// ---------------- scratch ----------------
__device__ float g_yw [ (size_t)ROWS * DIMC ];   // LN1 output, window order
__device__ float g_mw [ ROWS ];                  // clipped prior, window order
__device__ float g_qkv[ (size_t)ROWS * QKVC ];   // qkv, window order
__device__ float g_ao [ (size_t)ROWS * DIMC ];   // attention output, window order
__device__ float g_x1 [ (size_t)ROWS * DIMC ];   // shortcut + proj, (b,l) order
__device__ float g_ln2[ (size_t)ROWS * DIMC ];   // LN2 output, (b,l) order
__device__ float g_h  [ (size_t)ROWS * HID  ];   // fc1+gelu output

// ---------------- helpers ----------------
__device__ __forceinline__ uint32_t smem_to_u32(const void* smem_ptr) {
    uint32_t addr;
    asm("{ .reg .u64 tmp; cvta.to.shared.u64 tmp, %1; cvt.u32.u64 %0, tmp; }"
        : "=r"(addr) : "l"(smem_ptr));
    return addr;
}

#define CP_ASYNC16(dst, src) \
    asm volatile("cp.async.cg.shared.global [%0], [%1], 16;" \
        :: "r"(dst), "l"(src) : "memory")
#define CP_COMMIT() asm volatile("cp.async.commit_group;" ::: "memory")
#define CP_WAIT(n)  asm volatile("cp.async.wait_group " #n ";" ::: "memory")

// ---------------- LN1 + shift + window partition ----------------
__global__ __launch_bounds__(256) void ln1_win_kernel(
    const float* __restrict__ x, const float* __restrict__ Mmap,
    const float* __restrict__ gamma, const float* __restrict__ beta)
{
    int warp = threadIdx.x >> 5, lane = threadIdx.x & 31;
    int row  = (blockIdx.x << 3) + warp;          // window-order row
    int bq   = row >> 12, local = row & 4095;
    int wloc = local >> 6, t = local & 63;
    int hh = (((wloc >> 3) << 3) + (t >> 3) + SHIFT_) & 63;  // original h
    int ww = (((wloc &  7) << 3) + (t &  7) + SHIFT_) & 63;  // original w
    size_t src = ((size_t)bq * 4096 + (size_t)hh * 64 + ww) * DIMC;

    const float4* xp = (const float4*)(x + src);
    float v[16];
    float s = 0.f, ss = 0.f;
#pragma unroll
    for (int i = 0; i < 4; i++) {
        float4 f = xp[i * 32 + lane];
        v[i*4+0]=f.x; v[i*4+1]=f.y; v[i*4+2]=f.z; v[i*4+3]=f.w;
        s  += f.x + f.y + f.z + f.w;
        ss += f.x*f.x + f.y*f.y + f.z*f.z + f.w*f.w;
    }
#pragma unroll
    for (int o = 16; o; o >>= 1) {
        s  += __shfl_xor_sync(0xffffffffu, s,  o);
        ss += __shfl_xor_sync(0xffffffffu, ss, o);
    }
    float mean = s * (1.f/512.f);
    float var  = ss * (1.f/512.f) - mean * mean;
    float rstd = rsqrtf(var + 1e-5f);

    float4* yp = (float4*)(g_yw + (size_t)row * DIMC);
    const float4* gp = (const float4*)gamma;
    const float4* bp = (const float4*)beta;
#pragma unroll
    for (int i = 0; i < 4; i++) {
        float4 g4 = gp[i*32+lane], b4 = bp[i*32+lane];
        float4 o4;
        o4.x = (v[i*4+0]-mean)*rstd*g4.x + b4.x;
        o4.y = (v[i*4+1]-mean)*rstd*g4.y + b4.y;
        o4.z = (v[i*4+2]-mean)*rstd*g4.z + b4.z;
        o4.w = (v[i*4+3]-mean)*rstd*g4.w + b4.w;
        yp[i*32+lane] = o4;
    }
    if (lane == 0) {
        float m = Mmap[(size_t)bq * 4096 + (size_t)hh * 64 + ww];
        g_mw[row] = fminf(fmaxf(m, 0.f), 1.f);
    }
}

// ---------------- LN2 ----------------
__global__ __launch_bounds__(256) void ln2_kernel(
    const float* __restrict__ gamma, const float* __restrict__ beta)
{
    int warp = threadIdx.x >> 5, lane = threadIdx.x & 31;
    int row  = (blockIdx.x << 3) + warp;

    const float4* xp = (const float4*)(g_x1 + (size_t)row * DIMC);
    float v[16];
    float s = 0.f, ss = 0.f;
#pragma unroll
    for (int i = 0; i < 4; i++) {
        float4 f = xp[i * 32 + lane];
        v[i*4+0]=f.x; v[i*4+1]=f.y; v[i*4+2]=f.z; v[i*4+3]=f.w;
        s  += f.x + f.y + f.z + f.w;
        ss += f.x*f.x + f.y*f.y + f.z*f.z + f.w*f.w;
    }
#pragma unroll
    for (int o = 16; o; o >>= 1) {
        s  += __shfl_xor_sync(0xffffffffu, s,  o);
        ss += __shfl_xor_sync(0xffffffffu, ss, o);
    }
    float mean = s * (1.f/512.f);
    float var  = ss * (1.f/512.f) - mean * mean;
    float rstd = rsqrtf(var + 1e-5f);

    float4* yp = (float4*)(g_ln2 + (size_t)row * DIMC);
    const float4* gp = (const float4*)gamma;
    const float4* bp = (const float4*)beta;
#pragma unroll
    for (int i = 0; i < 4; i++) {
        float4 g4 = gp[i*32+lane], b4 = bp[i*32+lane];
        float4 o4;
        o4.x = (v[i*4+0]-mean)*rstd*g4.x + b4.x;
        o4.y = (v[i*4+1]-mean)*rstd*g4.y + b4.y;
        o4.z = (v[i*4+2]-mean)*rstd*g4.z + b4.z;
        o4.w = (v[i*4+3]-mean)*rstd*g4.w + b4.w;
        yp[i*32+lane] = o4;
    }
}

// ---------------- tf32 mma.sync GEMM: C(MxN) = A(MxK) * W(NxK)^T + bias ----------------
// Tile 128x128, K-chunk 32, 8 warps, warp tile 64(M) x 32(N).
// SMEM per buffer: A 128x32 f32 (16KB, XOR-swizzled), B 128x32 f32 (16KB). 2 buffers = 64KB.
#define EPI_NONE 0
#define EPI_GELU 1
#define EPI_PROJ 2
#define EPI_RES  3

#define GEMM_SMEM 65536

// Load one 128x32 fp32 tile (G row-major with leading dim K) into swizzled smem.
// Row stride in smem = 128B (8 chunks of 16B); chunk c of row m stored at chunk (c ^ (m&7)).
__device__ __forceinline__ void load_tile_async(
    uint32_t sbase, const float* __restrict__ G, int row0, int K, int k0, int t)
{
#pragma unroll
    for (int r = 0; r < 4; r++) {
        int ch = t + r * 256;            // 0..1023
        int m  = ch >> 3;
        int c  = ch & 7;
        uint32_t dst = sbase + m * 128 + ((c ^ (m & 7)) << 4);
        const float* src = G + (size_t)(row0 + m) * K + k0 + c * 4;
        CP_ASYNC16(dst, src);
    }
}

template<int EPI>
__global__ __launch_bounds__(256, 2) void mma_gemm(
    const float* __restrict__ A, const float* __restrict__ W,
    const float* __restrict__ bias, float* __restrict__ C,
    int M, int N, int K, const float* __restrict__ aux)
{
    extern __shared__ float smf[];
    uint32_t sb = smem_to_u32(smf);
    int tid = threadIdx.x, wid = tid >> 5, lane = tid & 31;
    int m0 = blockIdx.y << 7, n0 = blockIdx.x << 7;
    int nc = K >> 5;

    float acc[4][4][4];
#pragma unroll
    for (int i = 0; i < 4; i++)
#pragma unroll
        for (int j = 0; j < 4; j++)
#pragma unroll
            for (int k = 0; k < 4; k++) acc[i][j][k] = 0.f;

    // prologue: chunk 0 -> buffer 0
    load_tile_async(sb,         A, m0, K, 0, tid);
    load_tile_async(sb + 16384, W, n0, K, 0, tid);
    CP_COMMIT();

    const int wm = wid & 1, wn = wid >> 1;
    const uint32_t aRow = (wm << 6) + (lane & 15);
    const uint32_t aHi  = lane >> 4;          // 0/1 (k 16B-chunk hi bit)
    const uint32_t aXor = lane & 7;
    const uint32_t bRow = (wn << 5) + (lane >> 2);
    const uint32_t bXor = (lane >> 2) & 7;
    const uint32_t bOff = (lane & 3) << 2;

    for (int c = 0; c < nc; c++) {
        int b = c & 1;
        if (c + 1 < nc) {
            uint32_t nb = sb + ((b ^ 1) ? 32768u : 0u);
            load_tile_async(nb,         A, m0, K, (c + 1) << 5, tid);
            load_tile_async(nb + 16384, W, n0, K, (c + 1) << 5, tid);
            CP_COMMIT();
            CP_WAIT(1);
        } else {
            CP_WAIT(0);
        }
        __syncthreads();

        uint32_t aB = sb + (b ? 32768u : 0u);
        uint32_t bB = aB + 16384u;

#pragma unroll
        for (int ks = 0; ks < 4; ks++) {
            uint32_t a[4][4];
#pragma unroll
            for (int ma = 0; ma < 4; ma++) {
                uint32_t addr = aB + (aRow + ma * 16) * 128
                              + ((((ks << 1) + aHi) ^ aXor) << 4);
                asm volatile(
                    "ldmatrix.sync.aligned.m8n8.x4.shared.b16 {%0,%1,%2,%3}, [%4];"
                    : "=r"(a[ma][0]), "=r"(a[ma][1]), "=r"(a[ma][2]), "=r"(a[ma][3])
                    : "r"(addr));
            }
            uint32_t bf[4][2];
#pragma unroll
            for (int na = 0; na < 4; na++) {
                uint32_t rb = bB + (bRow + na * 8) * 128;
                uint32_t ad0 = rb + (((ks << 1)     ^ bXor) << 4) + bOff;
                uint32_t ad1 = rb + ((((ks << 1)|1) ^ bXor) << 4) + bOff;
                asm volatile("ld.shared.b32 %0, [%1];" : "=r"(bf[na][0]) : "r"(ad0));
                asm volatile("ld.shared.b32 %0, [%1];" : "=r"(bf[na][1]) : "r"(ad1));
            }
#pragma unroll
            for (int ma = 0; ma < 4; ma++)
#pragma unroll
                for (int na = 0; na < 4; na++) {
                    asm volatile(
                        "mma.sync.aligned.m16n8k8.row.col.f32.tf32.tf32.f32 "
                        "{%0,%1,%2,%3}, {%4,%5,%6,%7}, {%8,%9}, {%0,%1,%2,%3};"
                        : "+f"(acc[ma][na][0]), "+f"(acc[ma][na][1]),
                          "+f"(acc[ma][na][2]), "+f"(acc[ma][na][3])
                        : "r"(a[ma][0]), "r"(a[ma][1]), "r"(a[ma][2]), "r"(a[ma][3]),
                          "r"(bf[na][0]), "r"(bf[na][1]));
                }
        }
        __syncthreads();
    }

    // ---------------- epilogue (from registers) ----------------
    const int rBase = m0 + (wm << 6) + (lane >> 2);
    const int cBase = n0 + (wn << 5) + ((lane & 3) << 1);

    float bv[4][2];
#pragma unroll
    for (int na = 0; na < 4; na++) {
        bv[na][0] = __ldg(&bias[cBase + na * 8]);
        bv[na][1] = __ldg(&bias[cBase + na * 8 + 1]);
    }

#pragma unroll
    for (int ma = 0; ma < 4; ma++) {
#pragma unroll
        for (int half = 0; half < 2; half++) {
            int m = rBase + ma * 16 + half * 8;
            size_t obase;
            if (EPI == EPI_PROJ) {
                int bq = m >> 12, local = m & 4095;
                int wloc = local >> 6, t = local & 63;
                int hh = (((wloc >> 3) << 3) + (t >> 3) + SHIFT_) & 63;
                int ww = (((wloc &  7) << 3) + (t &  7) + SHIFT_) & 63;
                obase = ((size_t)bq * 4096 + (size_t)hh * 64 + ww) * DIMC;
            } else {
                obase = (size_t)m * N;
            }
#pragma unroll
            for (int na = 0; na < 4; na++) {
                int col = cBase + na * 8;
                float v0 = acc[ma][na][half * 2 + 0] + bv[na][0];
                float v1 = acc[ma][na][half * 2 + 1] + bv[na][1];
                if (EPI == EPI_GELU) {
                    v0 = 0.5f * v0 * (1.f + erff(v0 * 0.70710678118654752f));
                    v1 = 0.5f * v1 * (1.f + erff(v1 * 0.70710678118654752f));
                }
                size_t o = obase + col;
                if (EPI == EPI_PROJ || EPI == EPI_RES) {
                    float2 r2 = *(const float2*)(aux + o);
                    v0 += r2.x; v1 += r2.y;
                }
                float2 o2; o2.x = v0; o2.y = v1;
                *(float2*)(C + o) = o2;
            }
        }
    }
}

// ---------------- attention per (window, head) ----------------
__global__ __launch_bounds__(256) void attn_kernel(const float* __restrict__ rpb_table)
{
    __shared__ float qs[64][33];
    __shared__ float ks[64][33];
    __shared__ float vs[64][33];
    __shared__ float sc[64][65];
    __shared__ float rpb[225];
    __shared__ float mhalf[64];
    __shared__ int   rid[64];

    int w   = blockIdx.x >> 4;     // window id 0..1023
    int h   = blockIdx.x & 15;     // head
    int tid = threadIdx.x;

    size_t base = (size_t)w * 64 * QKVC + (size_t)h * HD;
#pragma unroll
    for (int e = tid; e < 2048; e += 256) {
        int i = e >> 5, d = e & 31;
        size_t o = base + (size_t)i * QKVC + d;
        qs[i][d] = g_qkv[o];
        ks[i][d] = g_qkv[o + 512];
        vs[i][d] = g_qkv[o + 1024];
    }
    for (int e = tid; e < 225; e += 256) rpb[e] = rpb_table[e * NHEAD + h];
    if (tid < 64) {
        mhalf[tid] = 0.5f * g_mw[w * 64 + tid];
        int wloc = w & 63;
        int hr = ((wloc >> 3) << 3) + (tid >> 3);
        int wr = ((wloc & 7)  << 3) + (tid & 7);
        int rh = hr < 56 ? 0 : (hr < 60 ? 1 : 2);
        int rw = wr < 56 ? 0 : (wr < 60 ? 1 : 2);
        rid[tid] = rh * 3 + rw;
    }
    __syncthreads();

    // ---- phase 1: scores ----
    {
        int i  = tid >> 2;
        int j0 = (tid & 3) * 16;
        float qreg[32];
#pragma unroll
        for (int d = 0; d < 32; d++) qreg[d] = qs[i][d];
        int ii = i >> 3, ji = i & 7;
        int ridi = rid[i];
        float mi = mhalf[i];
#pragma unroll 4
        for (int jj = 0; jj < 16; jj++) {
            int j = j0 + jj;
            float a = 0.f;
#pragma unroll
            for (int d = 0; d < 32; d++) a += qreg[d] * ks[j][d];
            int idx = (ii - (j >> 3) + 7) * 15 + (ji - (j & 7) + 7);
            float val = a * 0.17677669529663687f + rpb[idx] + mi + mhalf[j];
            if (ridi != rid[j]) val -= 100.f;
            sc[i][j] = val;
        }
    }
    __syncthreads();

    // ---- phase 2: softmax per row ----
    if (tid < 64) {
        float mx = -1e30f;
#pragma unroll 8
        for (int j = 0; j < 64; j++) mx = fmaxf(mx, sc[tid][j]);
        float ssum = 0.f;
#pragma unroll 8
        for (int j = 0; j < 64; j++) {
            float e = __expf(sc[tid][j] - mx);
            sc[tid][j] = e;
            ssum += e;
        }
        float inv = 1.f / ssum;
#pragma unroll 8
        for (int j = 0; j < 64; j++) sc[tid][j] *= inv;
    }
    __syncthreads();

    // ---- phase 3: P @ V ----
    {
        int oi = tid >> 2;
        int dg = (tid & 3) * 8;
        float acc[8];
#pragma unroll
        for (int d = 0; d < 8; d++) acc[d] = 0.f;
#pragma unroll 8
        for (int j = 0; j < 64; j++) {
            float p = sc[oi][j];
#pragma unroll
            for (int d = 0; d < 8; d++) acc[d] += p * vs[j][dg + d];
        }
        size_t ob = (size_t)(w * 64 + oi) * DIMC + (size_t)h * HD + dg;
#pragma unroll
        for (int d = 0; d < 8; d++) g_ao[ob + d] = acc[d];
    }
}

// ---------------- launcher ----------------
extern "C" void kernel_launch(void* const* d_in, const int* in_sizes, int n_in,
                              void* d_out, int out_size)
{
    (void)in_sizes; (void)n_in; (void)out_size;
    const float* x       = (const float*)d_in[0];
    const float* M_map   = (const float*)d_in[1];
    const float* n1g     = (const float*)d_in[2];
    const float* n1b     = (const float*)d_in[3];
    const float* qkv_w   = (const float*)d_in[4];
    const float* qkv_b   = (const float*)d_in[5];
    const float* proj_w  = (const float*)d_in[6];
    const float* proj_b  = (const float*)d_in[7];
    const float* rpb_t   = (const float*)d_in[8];
    const float* n2g     = (const float*)d_in[9];
    const float* n2b     = (const float*)d_in[10];
    const float* fc1_w   = (const float*)d_in[11];
    const float* fc1_b   = (const float*)d_in[12];
    const float* fc2_w   = (const float*)d_in[13];
    const float* fc2_b   = (const float*)d_in[14];
    float* out = (float*)d_out;

    void *p_yw, *p_qkv, *p_ao, *p_x1, *p_ln2, *p_h;
    cudaGetSymbolAddress(&p_yw,  g_yw);
    cudaGetSymbolAddress(&p_qkv, g_qkv);
    cudaGetSymbolAddress(&p_ao,  g_ao);
    cudaGetSymbolAddress(&p_x1,  g_x1);
    cudaGetSymbolAddress(&p_ln2, g_ln2);
    cudaGetSymbolAddress(&p_h,   g_h);

    cudaFuncSetAttribute(mma_gemm<EPI_NONE>, cudaFuncAttributeMaxDynamicSharedMemorySize, GEMM_SMEM);
    cudaFuncSetAttribute(mma_gemm<EPI_GELU>, cudaFuncAttributeMaxDynamicSharedMemorySize, GEMM_SMEM);
    cudaFuncSetAttribute(mma_gemm<EPI_PROJ>, cudaFuncAttributeMaxDynamicSharedMemorySize, GEMM_SMEM);
    cudaFuncSetAttribute(mma_gemm<EPI_RES>,  cudaFuncAttributeMaxDynamicSharedMemorySize, GEMM_SMEM);

    // 1) LN1 + shift + window partition (+ prior map)
    ln1_win_kernel<<<ROWS / 8, 256>>>(x, M_map, n1g, n1b);

    // 2) QKV GEMM: (65536 x 512) @ (1536 x 512)^T
    mma_gemm<EPI_NONE><<<dim3(QKVC / 128, ROWS / 128), 256, GEMM_SMEM>>>(
        (const float*)p_yw, qkv_w, qkv_b, (float*)p_qkv, ROWS, QKVC, DIMC, nullptr);

    // 3) windowed attention
    attn_kernel<<<1024 * NHEAD, 256>>>(rpb_t);

    // 4) proj GEMM + window-reverse + residual -> g_x1 (b,l) order
    mma_gemm<EPI_PROJ><<<dim3(DIMC / 128, ROWS / 128), 256, GEMM_SMEM>>>(
        (const float*)p_ao, proj_w, proj_b, (float*)p_x1, ROWS, DIMC, DIMC, x);

    // 5) LN2
    ln2_kernel<<<ROWS / 8, 256>>>(n2g, n2b);

    // 6) fc1 + GELU
    mma_gemm<EPI_GELU><<<dim3(HID / 128, ROWS / 128), 256, GEMM_SMEM>>>(
        (const float*)p_ln2, fc1_w, fc1_b, (float*)p_h, ROWS, HID, DIMC, nullptr);

    // 7) fc2 + residual -> d_out
    mma_gemm<EPI_RES><<<dim3(DIMC / 128, ROWS / 128), 256, GEMM_SMEM>>>(
        (const float*)p_h, fc2_w, fc2_b, out, ROWS, DIMC, HID, (const float*)p_x1);
}

// round 6
// speedup vs baseline: 3.6266x; 1.0376x over previous
#include <cuda_runtime.h>
#include <math.h>
#include <stdint.h>

// ---------------- constants ----------------
#define DIMC   512
#define NHEAD  16
#define HD     32
#define SHIFT_ 4
#define ROWS   65536       // B * L
#define HID    2048
#define QKVC   1536

// ---------------- scratch ----------------
__device__ float g_yw [ (size_t)ROWS * DIMC ];   // LN1 output, window order
__device__ float g_mw [ ROWS ];                  // clipped prior, window order
__device__ float g_qkv[ (size_t)ROWS * QKVC ];   // qkv, window order
__device__ float g_ao [ (size_t)ROWS * DIMC ];   // attention output, window order
__device__ float g_x1 [ (size_t)ROWS * DIMC ];   // shortcut + proj, (b,l) order
__device__ float g_ln2[ (size_t)ROWS * DIMC ];   // LN2 output, (b,l) order
__device__ float g_h  [ (size_t)ROWS * HID  ];   // fc1+gelu output

// ---------------- helpers ----------------
__device__ __forceinline__ uint32_t smem_to_u32(const void* smem_ptr) {
    uint32_t addr;
    asm("{ .reg .u64 tmp; cvta.to.shared.u64 tmp, %1; cvt.u32.u64 %0, tmp; }"
        : "=r"(addr) : "l"(smem_ptr));
    return addr;
}

#define CP_ASYNC16(dst, src) \
    asm volatile("cp.async.cg.shared.global [%0], [%1], 16;" \
        :: "r"(dst), "l"(src) : "memory")
#define CP_COMMIT() asm volatile("cp.async.commit_group;" ::: "memory")
#define CP_WAIT(n)  asm volatile("cp.async.wait_group " #n ";" ::: "memory")

// ---------------- LN1 + shift + window partition ----------------
__global__ __launch_bounds__(256) void ln1_win_kernel(
    const float* __restrict__ x, const float* __restrict__ Mmap,
    const float* __restrict__ gamma, const float* __restrict__ beta)
{
    int warp = threadIdx.x >> 5, lane = threadIdx.x & 31;
    int row  = (blockIdx.x << 3) + warp;          // window-order row
    int bq   = row >> 12, local = row & 4095;
    int wloc = local >> 6, t = local & 63;
    int hh = (((wloc >> 3) << 3) + (t >> 3) + SHIFT_) & 63;  // original h
    int ww = (((wloc &  7) << 3) + (t &  7) + SHIFT_) & 63;  // original w
    size_t src = ((size_t)bq * 4096 + (size_t)hh * 64 + ww) * DIMC;

    const float4* xp = (const float4*)(x + src);
    float v[16];
    float s = 0.f, ss = 0.f;
#pragma unroll
    for (int i = 0; i < 4; i++) {
        float4 f = xp[i * 32 + lane];
        v[i*4+0]=f.x; v[i*4+1]=f.y; v[i*4+2]=f.z; v[i*4+3]=f.w;
        s  += f.x + f.y + f.z + f.w;
        ss += f.x*f.x + f.y*f.y + f.z*f.z + f.w*f.w;
    }
#pragma unroll
    for (int o = 16; o; o >>= 1) {
        s  += __shfl_xor_sync(0xffffffffu, s,  o);
        ss += __shfl_xor_sync(0xffffffffu, ss, o);
    }
    float mean = s * (1.f/512.f);
    float var  = ss * (1.f/512.f) - mean * mean;
    float rstd = rsqrtf(var + 1e-5f);

    float4* yp = (float4*)(g_yw + (size_t)row * DIMC);
    const float4* gp = (const float4*)gamma;
    const float4* bp = (const float4*)beta;
#pragma unroll
    for (int i = 0; i < 4; i++) {
        float4 g4 = gp[i*32+lane], b4 = bp[i*32+lane];
        float4 o4;
        o4.x = (v[i*4+0]-mean)*rstd*g4.x + b4.x;
        o4.y = (v[i*4+1]-mean)*rstd*g4.y + b4.y;
        o4.z = (v[i*4+2]-mean)*rstd*g4.z + b4.z;
        o4.w = (v[i*4+3]-mean)*rstd*g4.w + b4.w;
        yp[i*32+lane] = o4;
    }
    if (lane == 0) {
        float m = Mmap[(size_t)bq * 4096 + (size_t)hh * 64 + ww];
        g_mw[row] = fminf(fmaxf(m, 0.f), 1.f);
    }
}

// ---------------- LN2 ----------------
__global__ __launch_bounds__(256) void ln2_kernel(
    const float* __restrict__ gamma, const float* __restrict__ beta)
{
    int warp = threadIdx.x >> 5, lane = threadIdx.x & 31;
    int row  = (blockIdx.x << 3) + warp;

    const float4* xp = (const float4*)(g_x1 + (size_t)row * DIMC);
    float v[16];
    float s = 0.f, ss = 0.f;
#pragma unroll
    for (int i = 0; i < 4; i++) {
        float4 f = xp[i * 32 + lane];
        v[i*4+0]=f.x; v[i*4+1]=f.y; v[i*4+2]=f.z; v[i*4+3]=f.w;
        s  += f.x + f.y + f.z + f.w;
        ss += f.x*f.x + f.y*f.y + f.z*f.z + f.w*f.w;
    }
#pragma unroll
    for (int o = 16; o; o >>= 1) {
        s  += __shfl_xor_sync(0xffffffffu, s,  o);
        ss += __shfl_xor_sync(0xffffffffu, ss, o);
    }
    float mean = s * (1.f/512.f);
    float var  = ss * (1.f/512.f) - mean * mean;
    float rstd = rsqrtf(var + 1e-5f);

    float4* yp = (float4*)(g_ln2 + (size_t)row * DIMC);
    const float4* gp = (const float4*)gamma;
    const float4* bp = (const float4*)beta;
#pragma unroll
    for (int i = 0; i < 4; i++) {
        float4 g4 = gp[i*32+lane], b4 = bp[i*32+lane];
        float4 o4;
        o4.x = (v[i*4+0]-mean)*rstd*g4.x + b4.x;
        o4.y = (v[i*4+1]-mean)*rstd*g4.y + b4.y;
        o4.z = (v[i*4+2]-mean)*rstd*g4.z + b4.z;
        o4.w = (v[i*4+3]-mean)*rstd*g4.w + b4.w;
        yp[i*32+lane] = o4;
    }
}

// ---------------- tf32 mma.sync GEMM: C(MxN) = A(MxK) * W(NxK)^T + bias ----------------
// Tile 128x128, K-chunk 32, 8 warps, warp tile 64(M) x 32(N).
// 3-stage cp.async pipeline. Stage = A 16KB + B 16KB = 32KB. Total 96KB.
#define EPI_NONE 0
#define EPI_GELU 1
#define EPI_PROJ 2
#define EPI_RES  3

#define STAGE_BYTES 32768
#define GEMM_SMEM   (3 * STAGE_BYTES)

// Load one 128x32 fp32 tile (G row-major with leading dim K) into swizzled smem.
// Row stride in smem = 128B (8 chunks of 16B); chunk c of row m stored at chunk (c ^ (m&7)).
__device__ __forceinline__ void load_tile_async(
    uint32_t sbase, const float* __restrict__ G, int row0, int K, int k0, int t)
{
#pragma unroll
    for (int r = 0; r < 4; r++) {
        int ch = t + r * 256;            // 0..1023
        int m  = ch >> 3;
        int c  = ch & 7;
        uint32_t dst = sbase + m * 128 + ((c ^ (m & 7)) << 4);
        const float* src = G + (size_t)(row0 + m) * K + k0 + c * 4;
        CP_ASYNC16(dst, src);
    }
}

template<int EPI>
__global__ __launch_bounds__(256, 2) void mma_gemm(
    const float* __restrict__ A, const float* __restrict__ W,
    const float* __restrict__ bias, float* __restrict__ C,
    int M, int N, int K, const float* __restrict__ aux)
{
    extern __shared__ float smf[];
    uint32_t sb = smem_to_u32(smf);
    int tid = threadIdx.x, wid = tid >> 5, lane = tid & 31;
    int m0 = blockIdx.y << 7, n0 = blockIdx.x << 7;
    int nc = K >> 5;

    float acc[4][4][4];
#pragma unroll
    for (int i = 0; i < 4; i++)
#pragma unroll
        for (int j = 0; j < 4; j++)
#pragma unroll
            for (int k = 0; k < 4; k++) acc[i][j][k] = 0.f;

    // prologue: chunks 0,1 -> stages 0,1
    load_tile_async(sb,                 A, m0, K, 0,  tid);
    load_tile_async(sb + 16384,         W, n0, K, 0,  tid);
    CP_COMMIT();
    load_tile_async(sb + STAGE_BYTES,         A, m0, K, 32, tid);
    load_tile_async(sb + STAGE_BYTES + 16384, W, n0, K, 32, tid);
    CP_COMMIT();

    const int wm = wid & 1, wn = wid >> 1;
    const uint32_t aRow = (wm << 6) + (lane & 15);
    const uint32_t aHi  = lane >> 4;          // 0/1 (k 16B-chunk hi bit)
    const uint32_t aXor = lane & 7;
    // B ldmatrix: thread t supplies row for submatrix t>>3, row t&7
    const uint32_t bMat = lane >> 3;          // 0..3
    const uint32_t bR   = lane & 7;
    const uint32_t bRowOff = ((bMat >> 1) << 3) + bR;   // row within 16-row pair
    const uint32_t bChunkLo = bMat & 1;

    for (int c = 0; c < nc; c++) {
        if (c + 2 < nc) {
            uint32_t nb = sb + (uint32_t)((c + 2) % 3) * STAGE_BYTES;
            load_tile_async(nb,         A, m0, K, (c + 2) << 5, tid);
            load_tile_async(nb + 16384, W, n0, K, (c + 2) << 5, tid);
            CP_COMMIT();
            CP_WAIT(2);
        } else if (c + 1 < nc) {
            CP_WAIT(1);
        } else {
            CP_WAIT(0);
        }
        __syncthreads();

        uint32_t aB = sb + (uint32_t)(c % 3) * STAGE_BYTES;
        uint32_t bB = aB + 16384u;

#pragma unroll
        for (int ks = 0; ks < 4; ks++) {
            uint32_t a[4][4];
#pragma unroll
            for (int ma = 0; ma < 4; ma++) {
                uint32_t addr = aB + (aRow + ma * 16) * 128
                              + ((((ks << 1) + aHi) ^ aXor) << 4);
                asm volatile(
                    "ldmatrix.sync.aligned.m8n8.x4.shared.b16 {%0,%1,%2,%3}, [%4];"
                    : "=r"(a[ma][0]), "=r"(a[ma][1]), "=r"(a[ma][2]), "=r"(a[ma][3])
                    : "r"(addr));
            }
            // B fragments via ldmatrix: pair p covers n-tiles 2p, 2p+1
            uint32_t bf[4][2];
#pragma unroll
            for (int p = 0; p < 2; p++) {
                uint32_t nrow = (wn << 5) + (p << 4) + bRowOff;
                uint32_t chunk = (ks << 1) + bChunkLo;
                uint32_t addr = bB + nrow * 128 + ((chunk ^ bR) << 4);
                asm volatile(
                    "ldmatrix.sync.aligned.m8n8.x4.shared.b16 {%0,%1,%2,%3}, [%4];"
                    : "=r"(bf[p*2][0]), "=r"(bf[p*2][1]),
                      "=r"(bf[p*2+1][0]), "=r"(bf[p*2+1][1])
                    : "r"(addr));
            }
#pragma unroll
            for (int ma = 0; ma < 4; ma++)
#pragma unroll
                for (int na = 0; na < 4; na++) {
                    asm volatile(
                        "mma.sync.aligned.m16n8k8.row.col.f32.tf32.tf32.f32 "
                        "{%0,%1,%2,%3}, {%4,%5,%6,%7}, {%8,%9}, {%0,%1,%2,%3};"
                        : "+f"(acc[ma][na][0]), "+f"(acc[ma][na][1]),
                          "+f"(acc[ma][na][2]), "+f"(acc[ma][na][3])
                        : "r"(a[ma][0]), "r"(a[ma][1]), "r"(a[ma][2]), "r"(a[ma][3]),
                          "r"(bf[na][0]), "r"(bf[na][1]));
                }
        }
        __syncthreads();
    }

    // ---------------- epilogue (from registers) ----------------
    const int rBase = m0 + (wm << 6) + (lane >> 2);
    const int cBase = n0 + (wn << 5) + ((lane & 3) << 1);

    float bv[4][2];
#pragma unroll
    for (int na = 0; na < 4; na++) {
        bv[na][0] = __ldg(&bias[cBase + na * 8]);
        bv[na][1] = __ldg(&bias[cBase + na * 8 + 1]);
    }

#pragma unroll
    for (int ma = 0; ma < 4; ma++) {
#pragma unroll
        for (int half = 0; half < 2; half++) {
            int m = rBase + ma * 16 + half * 8;
            size_t obase;
            if (EPI == EPI_PROJ) {
                int bq = m >> 12, local = m & 4095;
                int wloc = local >> 6, t = local & 63;
                int hh = (((wloc >> 3) << 3) + (t >> 3) + SHIFT_) & 63;
                int ww = (((wloc &  7) << 3) + (t &  7) + SHIFT_) & 63;
                obase = ((size_t)bq * 4096 + (size_t)hh * 64 + ww) * DIMC;
            } else {
                obase = (size_t)m * N;
            }
#pragma unroll
            for (int na = 0; na < 4; na++) {
                int col = cBase + na * 8;
                float v0 = acc[ma][na][half * 2 + 0] + bv[na][0];
                float v1 = acc[ma][na][half * 2 + 1] + bv[na][1];
                if (EPI == EPI_GELU) {
                    v0 = 0.5f * v0 * (1.f + erff(v0 * 0.70710678118654752f));
                    v1 = 0.5f * v1 * (1.f + erff(v1 * 0.70710678118654752f));
                }
                size_t o = obase + col;
                if (EPI == EPI_PROJ || EPI == EPI_RES) {
                    float2 r2 = *(const float2*)(aux + o);
                    v0 += r2.x; v1 += r2.y;
                }
                float2 o2; o2.x = v0; o2.y = v1;
                *(float2*)(C + o) = o2;
            }
        }
    }
}

// ---------------- attention per (window, head) ----------------
__global__ __launch_bounds__(256) void attn_kernel(const float* __restrict__ rpb_table)
{
    __shared__ float qs[64][33];
    __shared__ float ks[64][33];
    __shared__ float vs[64][33];
    __shared__ float sc[64][65];
    __shared__ float rpb[225];
    __shared__ float mhalf[64];
    __shared__ int   rid[64];

    int w   = blockIdx.x >> 4;     // window id 0..1023
    int h   = blockIdx.x & 15;     // head
    int tid = threadIdx.x;

    size_t base = (size_t)w * 64 * QKVC + (size_t)h * HD;
#pragma unroll
    for (int e = tid; e < 2048; e += 256) {
        int i = e >> 5, d = e & 31;
        size_t o = base + (size_t)i * QKVC + d;
        qs[i][d] = g_qkv[o];
        ks[i][d] = g_qkv[o + 512];
        vs[i][d] = g_qkv[o + 1024];
    }
    for (int e = tid; e < 225; e += 256) rpb[e] = rpb_table[e * NHEAD + h];
    if (tid < 64) {
        mhalf[tid] = 0.5f * g_mw[w * 64 + tid];
        int wloc = w & 63;
        int hr = ((wloc >> 3) << 3) + (tid >> 3);
        int wr = ((wloc & 7)  << 3) + (tid & 7);
        int rh = hr < 56 ? 0 : (hr < 60 ? 1 : 2);
        int rw = wr < 56 ? 0 : (wr < 60 ? 1 : 2);
        rid[tid] = rh * 3 + rw;
    }
    __syncthreads();

    // ---- phase 1: scores ----
    {
        int i  = tid >> 2;
        int j0 = (tid & 3) * 16;
        float qreg[32];
#pragma unroll
        for (int d = 0; d < 32; d++) qreg[d] = qs[i][d];
        int ii = i >> 3, ji = i & 7;
        int ridi = rid[i];
        float mi = mhalf[i];
#pragma unroll 4
        for (int jj = 0; jj < 16; jj++) {
            int j = j0 + jj;
            float a = 0.f;
#pragma unroll
            for (int d = 0; d < 32; d++) a += qreg[d] * ks[j][d];
            int idx = (ii - (j >> 3) + 7) * 15 + (ji - (j & 7) + 7);
            float val = a * 0.17677669529663687f + rpb[idx] + mi + mhalf[j];
            if (ridi != rid[j]) val -= 100.f;
            sc[i][j] = val;
        }
    }
    __syncthreads();

    // ---- phase 2: softmax per row ----
    if (tid < 64) {
        float mx = -1e30f;
#pragma unroll 8
        for (int j = 0; j < 64; j++) mx = fmaxf(mx, sc[tid][j]);
        float ssum = 0.f;
#pragma unroll 8
        for (int j = 0; j < 64; j++) {
            float e = __expf(sc[tid][j] - mx);
            sc[tid][j] = e;
            ssum += e;
        }
        float inv = 1.f / ssum;
#pragma unroll 8
        for (int j = 0; j < 64; j++) sc[tid][j] *= inv;
    }
    __syncthreads();

    // ---- phase 3: P @ V ----
    {
        int oi = tid >> 2;
        int dg = (tid & 3) * 8;
        float acc[8];
#pragma unroll
        for (int d = 0; d < 8; d++) acc[d] = 0.f;
#pragma unroll 8
        for (int j = 0; j < 64; j++) {
            float p = sc[oi][j];
#pragma unroll
            for (int d = 0; d < 8; d++) acc[d] += p * vs[j][dg + d];
        }
        size_t ob = (size_t)(w * 64 + oi) * DIMC + (size_t)h * HD + dg;
#pragma unroll
        for (int d = 0; d < 8; d++) g_ao[ob + d] = acc[d];
    }
}

// ---------------- launcher ----------------
extern "C" void kernel_launch(void* const* d_in, const int* in_sizes, int n_in,
                              void* d_out, int out_size)
{
    (void)in_sizes; (void)n_in; (void)out_size;
    const float* x       = (const float*)d_in[0];
    const float* M_map   = (const float*)d_in[1];
    const float* n1g     = (const float*)d_in[2];
    const float* n1b     = (const float*)d_in[3];
    const float* qkv_w   = (const float*)d_in[4];
    const float* qkv_b   = (const float*)d_in[5];
    const float* proj_w  = (const float*)d_in[6];
    const float* proj_b  = (const float*)d_in[7];
    const float* rpb_t   = (const float*)d_in[8];
    const float* n2g     = (const float*)d_in[9];
    const float* n2b     = (const float*)d_in[10];
    const float* fc1_w   = (const float*)d_in[11];
    const float* fc1_b   = (const float*)d_in[12];
    const float* fc2_w   = (const float*)d_in[13];
    const float* fc2_b   = (const float*)d_in[14];
    float* out = (float*)d_out;

    void *p_yw, *p_qkv, *p_ao, *p_x1, *p_ln2, *p_h;
    cudaGetSymbolAddress(&p_yw,  g_yw);
    cudaGetSymbolAddress(&p_qkv, g_qkv);
    cudaGetSymbolAddress(&p_ao,  g_ao);
    cudaGetSymbolAddress(&p_x1,  g_x1);
    cudaGetSymbolAddress(&p_ln2, g_ln2);
    cudaGetSymbolAddress(&p_h,   g_h);

    cudaFuncSetAttribute(mma_gemm<EPI_NONE>, cudaFuncAttributeMaxDynamicSharedMemorySize, GEMM_SMEM);
    cudaFuncSetAttribute(mma_gemm<EPI_GELU>, cudaFuncAttributeMaxDynamicSharedMemorySize, GEMM_SMEM);
    cudaFuncSetAttribute(mma_gemm<EPI_PROJ>, cudaFuncAttributeMaxDynamicSharedMemorySize, GEMM_SMEM);
    cudaFuncSetAttribute(mma_gemm<EPI_RES>,  cudaFuncAttributeMaxDynamicSharedMemorySize, GEMM_SMEM);

    // 1) LN1 + shift + window partition (+ prior map)
    ln1_win_kernel<<<ROWS / 8, 256>>>(x, M_map, n1g, n1b);

    // 2) QKV GEMM: (65536 x 512) @ (1536 x 512)^T
    mma_gemm<EPI_NONE><<<dim3(QKVC / 128, ROWS / 128), 256, GEMM_SMEM>>>(
        (const float*)p_yw, qkv_w, qkv_b, (float*)p_qkv, ROWS, QKVC, DIMC, nullptr);

    // 3) windowed attention
    attn_kernel<<<1024 * NHEAD, 256>>>(rpb_t);

    // 4) proj GEMM + window-reverse + residual -> g_x1 (b,l) order
    mma_gemm<EPI_PROJ><<<dim3(DIMC / 128, ROWS / 128), 256, GEMM_SMEM>>>(
        (const float*)p_ao, proj_w, proj_b, (float*)p_x1, ROWS, DIMC, DIMC, x);

    // 5) LN2
    ln2_kernel<<<ROWS / 8, 256>>>(n2g, n2b);

    // 6) fc1 + GELU
    mma_gemm<EPI_GELU><<<dim3(HID / 128, ROWS / 128), 256, GEMM_SMEM>>>(
        (const float*)p_ln2, fc1_w, fc1_b, (float*)p_h, ROWS, HID, DIMC, nullptr);

    // 7) fc2 + residual -> d_out
    mma_gemm<EPI_RES><<<dim3(DIMC / 128, ROWS / 128), 256, GEMM_SMEM>>>(
        (const float*)p_h, fc2_w, fc2_b, out, ROWS, DIMC, HID, (const float*)p_x1);
}